// round 9
// baseline (speedup 1.0000x reference)
#include <cuda_runtime.h>
#include <cstdint>

#define BN 64
#define BM 128
#define DD 128
#define PAD 132
#define THREADS 256
#define NMAX 4096
#define MMAX 16384
#define SLOTS 4

typedef unsigned long long u64;

__device__ float g_y2[MMAX];
__device__ float g_pev[SLOTS][NMAX][DD];
__device__ float g_pm[SLOTS][NMAX];
__device__ float g_ps[SLOTS][NMAX];

#define FMA2(d,a,b) asm("fma.rn.f32x2 %0,%1,%2,%0;" : "+l"(d) : "l"(a), "l"(b))
#define MUL2(d,a,b) asm("mul.rn.f32x2 %0,%1,%2;" : "=l"(d) : "l"(a), "l"(b))
#define UNPACK(lo,hi,p) asm("mov.b64 {%0,%1},%2;" : "=f"(lo), "=f"(hi) : "l"(p))
#define PACK(d,lo,hi) asm("mov.b64 %0,{%1,%2};" : "=l"(d) : "f"(lo), "f"(hi))
#define DUP(d,v) asm("mov.b64 %0,{%1,%1};" : "=l"(d) : "f"(v))

__global__ __launch_bounds__(256) void y2_kernel(const float* __restrict__ y, int M) {
    int gw   = (blockIdx.x * blockDim.x + threadIdx.x) >> 5;
    int lane = threadIdx.x & 31;
    if (gw >= M) return;
    float4 v = ((const float4*)(y + (size_t)gw * DD))[lane];
    float s = v.x * v.x + v.y * v.y + v.z * v.z + v.w * v.w;
#pragma unroll
    for (int o = 16; o; o >>= 1) s += __shfl_xor_sync(0xffffffffu, s, o);
    if (lane == 0) g_y2[gw] = s;
}

__device__ __forceinline__ void cpa16(float* dst, const float* src) {
    uint32_t s = (uint32_t)__cvta_generic_to_shared(dst);
    asm volatile("cp.async.cg.shared.global [%0], [%1], 16;" :: "r"(s), "l"(src));
}

__global__ __launch_bounds__(THREADS, 1) void gmm_kernel(
    const float* __restrict__ x, const float* __restrict__ t,
    const float* __restrict__ y, int M, int N)
{
    extern __shared__ float sm[];
    float* x_s = sm;                       // BN*PAD (A-scaled x)
    float* y_n = x_s + BN * PAD;           // 2 * BM * PAD
    float* w_s = y_n + 2 * BM * PAD;       // 8 warps * BM * 8
    float* y2s = w_s + 8 * BM * 8;         // 2 * BM
    float* sA  = y2s + 2 * BM;             // BN
    float* sC  = sA + BN;                  // BN

    const int tid  = threadIdx.x;
    const int lane = tid & 31;
    const int w    = tid >> 5;
    const int r0   = w * 8;
    float* w_w = w_s + w * (BM * 8);

    const int NT = M / BM;                 // tiles per job (128)
    const int NJ = N / BN;                 // jobs (64)
    const int T  = NJ * NT;                // total units
    const int P  = gridDim.x;
    const int c  = blockIdx.x;
    const int u0 = (int)((long long)c * T / P);
    const int u1 = (int)((long long)(c + 1) * T / P);
    if (u0 >= u1) return;

    auto load_tile = [&](int b, int u) {
        int tile = u % NT;
        float* buf = y_n + b * (BM * PAD);
        const float* src = y + (size_t)tile * BM * DD;
#pragma unroll
        for (int i = tid; i < BM * DD / 4; i += THREADS) {
            int j = i >> 5, cc = i & 31;
            cpa16(&buf[j * PAD + 4 * cc], src + j * DD + 4 * cc);
        }
        if (tid < BM / 4) cpa16(&y2s[b * BM + 4 * tid], g_y2 + tile * BM + 4 * tid);
        asm volatile("cp.async.commit_group;");
    };

    load_tile(0, u0);
    int b = 0;
    int u = u0;

    while (u < u1) {
        const int job = u / NT;
        const int jend = min(u1, (job + 1) * NT);
        const int n0 = job * BN;

        // ---- per-job setup: row constants + A-scaled x ----
        if (tid < BN) {
            float tt = t[n0 + tid];
            float lm = -0.25f * tt * tt * (20.0f - 0.1f) - 0.5f * tt * 0.1f;
            float mean = expf(lm);
            float var  = fmaxf(1.0f - expf(2.0f * lm), 1e-12f);
            float iv   = 1.0f / var;
            sA[tid] = iv * mean;
            sC[tid] = -0.5f * iv * mean * mean;
        }
        __syncthreads();
#pragma unroll
        for (int i = tid; i < BN * DD / 4; i += THREADS) {
            int r = i >> 5, cc = i & 31;
            float4 v = ((const float4*)(x + (size_t)(n0 + r) * DD))[cc];
            float a = sA[r];
            v.x *= a; v.y *= a; v.z *= a; v.w *= a;
            *(float4*)&x_s[r * PAD + 4 * cc] = v;
        }

        float C[8];
#pragma unroll
        for (int i = 0; i < 8; i++) C[i] = sC[r0 + i];

        u64 ev[4][4];
#pragma unroll
        for (int a = 0; a < 4; a++)
#pragma unroll
            for (int d = 0; d < 4; d++) ev[a][d] = 0ULL;
        float mrow[8], srow[8];
        const float NEG_INF = __int_as_float(0xff800000);
#pragma unroll
        for (int i = 0; i < 8; i++) { mrow[i] = NEG_INF; srow[i] = 0.0f; }

        for (; u < jend; ++u) {
            if (u + 1 < u1) {
                load_tile(b ^ 1, u + 1);
                asm volatile("cp.async.wait_group 1;");
            } else {
                asm volatile("cp.async.wait_group 0;");
            }
            __syncthreads();

            float* buf = y_n + b * (BM * PAD);

            // ---- GEMM1: 8 rows x 4 cols, packed f32x2 over k ----
            u64 acc[8][4];
#pragma unroll
            for (int i = 0; i < 8; i++)
#pragma unroll
                for (int cc = 0; cc < 4; cc++) acc[i][cc] = 0ULL;

#pragma unroll 2
            for (int k = 0; k < DD; k += 4) {
                ulonglong2 yv0 = *(const ulonglong2*)&buf[(lane      ) * PAD + k];
                ulonglong2 yv1 = *(const ulonglong2*)&buf[(lane +  32) * PAD + k];
                ulonglong2 yv2 = *(const ulonglong2*)&buf[(lane +  64) * PAD + k];
                ulonglong2 yv3 = *(const ulonglong2*)&buf[(lane +  96) * PAD + k];
#pragma unroll
                for (int h = 0; h < 2; h++) {
                    ulonglong2 xv[4];
#pragma unroll
                    for (int i = 0; i < 4; i++)
                        xv[i] = *(const ulonglong2*)&x_s[(r0 + 4 * h + i) * PAD + k];
#pragma unroll
                    for (int i = 0; i < 4; i++) {
                        FMA2(acc[4 * h + i][0], xv[i].x, yv0.x);
                        FMA2(acc[4 * h + i][1], xv[i].x, yv1.x);
                        FMA2(acc[4 * h + i][2], xv[i].x, yv2.x);
                        FMA2(acc[4 * h + i][3], xv[i].x, yv3.x);
                    }
#pragma unroll
                    for (int i = 0; i < 4; i++) {
                        FMA2(acc[4 * h + i][0], xv[i].y, yv0.y);
                        FMA2(acc[4 * h + i][1], xv[i].y, yv1.y);
                        FMA2(acc[4 * h + i][2], xv[i].y, yv2.y);
                        FMA2(acc[4 * h + i][3], xv[i].y, yv3.y);
                    }
                }
            }

            // ---- logits ----
            float lv[8][4];
#pragma unroll
            for (int i = 0; i < 8; i++)
#pragma unroll
                for (int cc = 0; cc < 4; cc++) {
                    float lo, hi; UNPACK(lo, hi, acc[i][cc]);
                    lv[i][cc] = lo + hi;
                }
            float y2v[4];
#pragma unroll
            for (int cc = 0; cc < 4; cc++) y2v[cc] = y2s[b * BM + lane + 32 * cc];
#pragma unroll
            for (int i = 0; i < 8; i++)
#pragma unroll
                for (int cc = 0; cc < 4; cc++) lv[i][cc] = fmaf(C[i], y2v[cc], lv[i][cc]);

            // ---- per-warp online softmax ----
            float mx[8];
#pragma unroll
            for (int i = 0; i < 8; i++)
                mx[i] = fmaxf(fmaxf(lv[i][0], lv[i][1]), fmaxf(lv[i][2], lv[i][3]));
#pragma unroll
            for (int o = 16; o; o >>= 1)
#pragma unroll
                for (int i = 0; i < 8; i++)
                    mx[i] = fmaxf(mx[i], __shfl_xor_sync(0xffffffffu, mx[i], o));

            float scl[8], ps[8];
#pragma unroll
            for (int i = 0; i < 8; i++) {
                float mn = fmaxf(mrow[i], mx[i]);
                scl[i] = __expf(mrow[i] - mn);
                mrow[i] = mn;
            }
            float pv[8][4];
#pragma unroll
            for (int i = 0; i < 8; i++) {
#pragma unroll
                for (int cc = 0; cc < 4; cc++) pv[i][cc] = __expf(lv[i][cc] - mrow[i]);
                ps[i] = (pv[i][0] + pv[i][1]) + (pv[i][2] + pv[i][3]);
            }
#pragma unroll
            for (int o = 16; o; o >>= 1)
#pragma unroll
                for (int i = 0; i < 8; i++)
                    ps[i] += __shfl_xor_sync(0xffffffffu, ps[i], o);
#pragma unroll
            for (int i = 0; i < 8; i++) srow[i] = fmaf(srow[i], scl[i], ps[i]);

#pragma unroll
            for (int a = 0; a < 4; a++) {
                u64 s2; PACK(s2, scl[2 * a], scl[2 * a + 1]);
#pragma unroll
                for (int d = 0; d < 4; d++) MUL2(ev[a][d], ev[a][d], s2);
            }

#pragma unroll
            for (int cc = 0; cc < 4; cc++) {
                int j = lane + 32 * cc;
                *(float4*)&w_w[8 * j]     = make_float4(pv[0][cc], pv[1][cc], pv[2][cc], pv[3][cc]);
                *(float4*)&w_w[8 * j + 4] = make_float4(pv[4][cc], pv[5][cc], pv[6][cc], pv[7][cc]);
            }
            __syncwarp();

            // ---- GEMM2 ----
#pragma unroll 2
            for (int j = 0; j < BM; j++) {
                ulonglong2 wa = *(const ulonglong2*)&w_w[8 * j];
                ulonglong2 wb = *(const ulonglong2*)&w_w[8 * j + 4];
                ulonglong2 yv = *(const ulonglong2*)&buf[j * PAD + 4 * lane];
                float q0, q1, q2, q3;
                UNPACK(q0, q1, yv.x);
                UNPACK(q2, q3, yv.y);
                u64 d0, d1, d2, d3;
                DUP(d0, q0); DUP(d1, q1); DUP(d2, q2); DUP(d3, q3);
                FMA2(ev[0][0], wa.x, d0); FMA2(ev[0][1], wa.x, d1);
                FMA2(ev[0][2], wa.x, d2); FMA2(ev[0][3], wa.x, d3);
                FMA2(ev[1][0], wa.y, d0); FMA2(ev[1][1], wa.y, d1);
                FMA2(ev[1][2], wa.y, d2); FMA2(ev[1][3], wa.y, d3);
                FMA2(ev[2][0], wb.x, d0); FMA2(ev[2][1], wb.x, d1);
                FMA2(ev[2][2], wb.x, d2); FMA2(ev[2][3], wb.x, d3);
                FMA2(ev[3][0], wb.y, d0); FMA2(ev[3][1], wb.y, d1);
                FMA2(ev[3][2], wb.y, d2); FMA2(ev[3][3], wb.y, d3);
            }
            __syncthreads();
            b ^= 1;
        }

        // ---- flush partial for this job segment ----
        int c0 = ((job * NT + 1) * P - 1) / T;   // first CTA touching this job
        int slot = c - c0;
#pragma unroll
        for (int a = 0; a < 4; a++) {
            float e0[4], e1[4];
#pragma unroll
            for (int d = 0; d < 4; d++) UNPACK(e0[d], e1[d], ev[a][d]);
            *(float4*)&g_pev[slot][n0 + r0 + 2 * a    ][4 * lane] = make_float4(e0[0], e0[1], e0[2], e0[3]);
            *(float4*)&g_pev[slot][n0 + r0 + 2 * a + 1][4 * lane] = make_float4(e1[0], e1[1], e1[2], e1[3]);
        }
        if (lane == 0) {
#pragma unroll
            for (int i = 0; i < 8; i++) {
                g_pm[slot][n0 + r0 + i] = mrow[i];
                g_ps[slot][n0 + r0 + i] = srow[i];
            }
        }
        __syncthreads();   // before re-staging x_s / sA for next job
    }
}

__global__ __launch_bounds__(256) void combine_kernel(
    const float* __restrict__ x, const float* __restrict__ t,
    float* __restrict__ out, int N)
{
    int row  = blockIdx.x * 8 + (threadIdx.x >> 5);
    int lane = threadIdx.x & 31;
    if (row >= N) return;
    const float NEG_INF = __int_as_float(0xff800000);

    float m[SLOTS], s[SLOTS];
#pragma unroll
    for (int k = 0; k < SLOTS; k++) {
        s[k] = g_ps[k][row];
        // empty slot (never written this job): s==0 -> treat as -inf so its
        // stale m can't poison the max and its stale ev is multiplied by exp(-inf)=0.
        m[k] = (s[k] > 0.0f) ? g_pm[k][row] : NEG_INF;
    }
    float mxv = m[0];
#pragma unroll
    for (int k = 1; k < SLOTS; k++) mxv = fmaxf(mxv, m[k]);
    float a[SLOTS];
    float denom = 0.0f;
#pragma unroll
    for (int k = 0; k < SLOTS; k++) { a[k] = __expf(m[k] - mxv); denom = fmaf(s[k], a[k], denom); }
    float inv = 1.0f / denom;

    float tt = t[row];
    float lm = -0.25f * tt * tt * (20.0f - 0.1f) - 0.5f * tt * 0.1f;
    float var = fmaxf(1.0f - expf(2.0f * lm), 1e-12f);
    float iv = 1.0f / var;

    float4 acc = make_float4(0.f, 0.f, 0.f, 0.f);
#pragma unroll
    for (int k = 0; k < SLOTS; k++) {
        float4 e = ((const float4*)g_pev[k][row])[lane];
        acc.x = fmaf(e.x, a[k], acc.x);
        acc.y = fmaf(e.y, a[k], acc.y);
        acc.z = fmaf(e.z, a[k], acc.z);
        acc.w = fmaf(e.w, a[k], acc.w);
    }
    float4 xv = ((const float4*)(x + (size_t)row * DD))[lane];
    float4 o;
    o.x = (acc.x * inv - xv.x) * iv;
    o.y = (acc.y * inv - xv.y) * iv;
    o.z = (acc.z * inv - xv.z) * iv;
    o.w = (acc.w * inv - xv.w) * iv;
    ((float4*)(out + (size_t)row * DD))[lane] = o;
}

extern "C" void kernel_launch(void* const* d_in, const int* in_sizes, int n_in,
                              void* d_out, int out_size) {
    const float* x = (const float*)d_in[0];
    const float* t = (const float*)d_in[1];
    const float* y = (const float*)d_in[2];
    float* out = (float*)d_out;
    const int N = in_sizes[1];
    const int M = in_sizes[2] / DD;

    size_t smem = (size_t)(BN * PAD + 2 * BM * PAD + 8 * BM * 8 + 2 * BM + 2 * BN) * sizeof(float);
    cudaFuncSetAttribute(gmm_kernel, cudaFuncAttributeMaxDynamicSharedMemorySize, (int)smem);

    y2_kernel<<<(M + 7) / 8, 256>>>(y, M);
    gmm_kernel<<<148, THREADS, smem>>>(x, t, y, M, N);
    combine_kernel<<<(N + 7) / 8, 256>>>(x, t, out, N);
}

// round 10
// speedup vs baseline: 1.4730x; 1.4730x over previous
#include <cuda_runtime.h>
#include <cstdint>

#define BN 64
#define BM 128
#define DD 128
#define PAD 132
#define THREADS 512
#define NMAX 4096
#define MMAX 16384
#define SLOTS 2

typedef unsigned long long u64;

__device__ float g_y2[MMAX];
__device__ float g_pev[SLOTS][NMAX][DD];
__device__ float g_pm[SLOTS][NMAX];
__device__ float g_ps[SLOTS][NMAX];

#define FMA2(d,a,b) asm("fma.rn.f32x2 %0,%1,%2,%0;" : "+l"(d) : "l"(a), "l"(b))
#define MUL2(d,a,b) asm("mul.rn.f32x2 %0,%1,%2;" : "=l"(d) : "l"(a), "l"(b))
#define UNPACK(lo,hi,p) asm("mov.b64 {%0,%1},%2;" : "=f"(lo), "=f"(hi) : "l"(p))
#define PACK(d,lo,hi) asm("mov.b64 %0,{%1,%2};" : "=l"(d) : "f"(lo), "f"(hi))
#define DUP(d,v) asm("mov.b64 %0,{%1,%1};" : "=l"(d) : "f"(v))

__global__ __launch_bounds__(256) void y2_kernel(const float* __restrict__ y, int M) {
    int gw   = (blockIdx.x * blockDim.x + threadIdx.x) >> 5;
    int lane = threadIdx.x & 31;
    if (gw >= M) return;
    float4 v = ((const float4*)(y + (size_t)gw * DD))[lane];
    float s = v.x * v.x + v.y * v.y + v.z * v.z + v.w * v.w;
#pragma unroll
    for (int o = 16; o; o >>= 1) s += __shfl_xor_sync(0xffffffffu, s, o);
    if (lane == 0) g_y2[gw] = s;
}

// phase-shift no-op: makes launches-per-call == 4 so ncu (-s 5 -c 1) lands on gmm_kernel
__global__ void phase_kernel() {}

__device__ __forceinline__ void cpa16(float* dst, const float* src) {
    uint32_t s = (uint32_t)__cvta_generic_to_shared(dst);
    asm volatile("cp.async.cg.shared.global [%0], [%1], 16;" :: "r"(s), "l"(src));
}

__global__ __launch_bounds__(THREADS, 1) void gmm_kernel(
    const float* __restrict__ x, const float* __restrict__ t,
    const float* __restrict__ y, int M)
{
    extern __shared__ float sm[];
    float* x_s = sm;                       // BN*PAD (A-scaled x)
    float* y_n = x_s + BN * PAD;           // 2 * BM * PAD
    float* w_s = y_n + 2 * BM * PAD;       // 16 warps * BM * 4 (row-interleaved)
    float* y2s = w_s + 16 * BM * 4;        // 2 * BM
    float* sA  = y2s + 2 * BM;             // BN
    float* sC  = sA + BN;                  // BN

    const int tid  = threadIdx.x;
    const int lane = tid & 31;
    const int w    = tid >> 5;
    const int n0   = blockIdx.x * BN;
    const int half = blockIdx.y;
    const int halfM = M >> 1;
    const float* yg  = y + (size_t)half * halfM * DD;
    const float* y2g = g_y2 + (size_t)half * halfM;
    const int r0 = w * 4;                  // this warp's 4 rows
    float* w_w = w_s + w * (BM * 4);

    if (tid < BN) {
        float tt = t[n0 + tid];
        float lm = -0.25f * tt * tt * (20.0f - 0.1f) - 0.5f * tt * 0.1f;
        float mean = expf(lm);
        float var  = fmaxf(1.0f - expf(2.0f * lm), 1e-12f);
        float iv   = 1.0f / var;
        sA[tid] = iv * mean;
        sC[tid] = -0.5f * iv * mean * mean;
    }
    __syncthreads();

    // stage x pre-scaled by A (logit = <A*x, y> + C*y2)
#pragma unroll
    for (int i = tid; i < BN * DD / 4; i += THREADS) {
        int r = i >> 5, cc = i & 31;
        float4 v = ((const float4*)(x + (size_t)(n0 + r) * DD))[cc];
        float a = sA[r];
        v.x *= a; v.y *= a; v.z *= a; v.w *= a;
        *(float4*)&x_s[r * PAD + 4 * cc] = v;
    }

    float C[4];
#pragma unroll
    for (int i = 0; i < 4; i++) C[i] = sC[r0 + i];

    // ev pairs over row-pairs: ev[rp][d] = (row 2rp, row 2rp+1), d = 4 f32x2 = 8 floats... 
    // per thread output: 4 rows x 8 d-floats held as ev[2 row-pairs][4 packed-d]
    u64 ev[2][4];
#pragma unroll
    for (int a = 0; a < 2; a++)
#pragma unroll
        for (int d = 0; d < 4; d++) ev[a][d] = 0ULL;
    float mrow[4], srow[4];
    const float NEG_INF = __int_as_float(0xff800000);
#pragma unroll
    for (int i = 0; i < 4; i++) { mrow[i] = NEG_INF; srow[i] = 0.0f; }

    auto load_tile = [&](int b, int tile) {
        float* buf = y_n + b * (BM * PAD);
        const float* src = yg + (size_t)tile * BM * DD;
#pragma unroll
        for (int i = tid; i < BM * DD / 4; i += THREADS) {
            int j = i >> 5, cc = i & 31;
            cpa16(&buf[j * PAD + 4 * cc], src + j * DD + 4 * cc);
        }
        if (tid < BM / 4) cpa16(&y2s[b * BM + 4 * tid], y2g + tile * BM + 4 * tid);
        asm volatile("cp.async.commit_group;");
    };

    const int nt = halfM / BM;
    load_tile(0, 0);
    int b = 0;
    for (int it = 0; it < nt; ++it) {
        if (it + 1 < nt) {
            load_tile(b ^ 1, it + 1);
            asm volatile("cp.async.wait_group 1;");
        } else {
            asm volatile("cp.async.wait_group 0;");
        }
        __syncthreads();

        float* buf = y_n + b * (BM * PAD);

        // ---- GEMM1: 4 rows x 4 cols per thread, packed f32x2 over k ----
        u64 acc[4][4];
#pragma unroll
        for (int i = 0; i < 4; i++)
#pragma unroll
            for (int cc = 0; cc < 4; cc++) acc[i][cc] = 0ULL;

#pragma unroll 2
        for (int k = 0; k < DD; k += 4) {
            ulonglong2 yv0 = *(const ulonglong2*)&buf[(lane      ) * PAD + k];
            ulonglong2 yv1 = *(const ulonglong2*)&buf[(lane +  32) * PAD + k];
            ulonglong2 yv2 = *(const ulonglong2*)&buf[(lane +  64) * PAD + k];
            ulonglong2 yv3 = *(const ulonglong2*)&buf[(lane +  96) * PAD + k];
            ulonglong2 xv[4];
#pragma unroll
            for (int i = 0; i < 4; i++)
                xv[i] = *(const ulonglong2*)&x_s[(r0 + i) * PAD + k];
#pragma unroll
            for (int i = 0; i < 4; i++) {
                FMA2(acc[i][0], xv[i].x, yv0.x);
                FMA2(acc[i][1], xv[i].x, yv1.x);
                FMA2(acc[i][2], xv[i].x, yv2.x);
                FMA2(acc[i][3], xv[i].x, yv3.x);
            }
#pragma unroll
            for (int i = 0; i < 4; i++) {
                FMA2(acc[i][0], xv[i].y, yv0.y);
                FMA2(acc[i][1], xv[i].y, yv1.y);
                FMA2(acc[i][2], xv[i].y, yv2.y);
                FMA2(acc[i][3], xv[i].y, yv3.y);
            }
        }

        // ---- logits ----
        float lv[4][4];
#pragma unroll
        for (int i = 0; i < 4; i++)
#pragma unroll
            for (int cc = 0; cc < 4; cc++) {
                float lo, hi; UNPACK(lo, hi, acc[i][cc]);
                lv[i][cc] = lo + hi;
            }
        float y2v[4];
#pragma unroll
        for (int cc = 0; cc < 4; cc++) y2v[cc] = y2s[b * BM + lane + 32 * cc];
#pragma unroll
        for (int i = 0; i < 4; i++)
#pragma unroll
            for (int cc = 0; cc < 4; cc++) lv[i][cc] = fmaf(C[i], y2v[cc], lv[i][cc]);

        // ---- per-warp online softmax (4 row chains) ----
        float mx[4];
#pragma unroll
        for (int i = 0; i < 4; i++)
            mx[i] = fmaxf(fmaxf(lv[i][0], lv[i][1]), fmaxf(lv[i][2], lv[i][3]));
#pragma unroll
        for (int o = 16; o; o >>= 1)
#pragma unroll
            for (int i = 0; i < 4; i++)
                mx[i] = fmaxf(mx[i], __shfl_xor_sync(0xffffffffu, mx[i], o));

        float scl[4], ps[4];
#pragma unroll
        for (int i = 0; i < 4; i++) {
            float mn = fmaxf(mrow[i], mx[i]);
            scl[i] = __expf(mrow[i] - mn);
            mrow[i] = mn;
        }
        float pv[4][4];
#pragma unroll
        for (int i = 0; i < 4; i++) {
#pragma unroll
            for (int cc = 0; cc < 4; cc++) pv[i][cc] = __expf(lv[i][cc] - mrow[i]);
            ps[i] = (pv[i][0] + pv[i][1]) + (pv[i][2] + pv[i][3]);
        }
#pragma unroll
        for (int o = 16; o; o >>= 1)
#pragma unroll
            for (int i = 0; i < 4; i++)
                ps[i] += __shfl_xor_sync(0xffffffffu, ps[i], o);
#pragma unroll
        for (int i = 0; i < 4; i++) srow[i] = fmaf(srow[i], scl[i], ps[i]);

        // rescale ev accumulators (row pairs)
#pragma unroll
        for (int a = 0; a < 2; a++) {
            u64 s2; PACK(s2, scl[2 * a], scl[2 * a + 1]);
#pragma unroll
            for (int d = 0; d < 4; d++) MUL2(ev[a][d], ev[a][d], s2);
        }

        // store weights row-interleaved: w_w[4*j + r] = p[r][j]
#pragma unroll
        for (int cc = 0; cc < 4; cc++) {
            int j = lane + 32 * cc;
            *(float4*)&w_w[4 * j] = make_float4(pv[0][cc], pv[1][cc], pv[2][cc], pv[3][cc]);
        }
        __syncwarp();

        // ---- GEMM2: ev[row-pair][d] += (w_r0,w_r1) * (y_d,y_d) ----
#pragma unroll 4
        for (int j = 0; j < BM; j++) {
            ulonglong2 wa = *(const ulonglong2*)&w_w[4 * j];   // (w_r0,w_r1),(w_r2,w_r3)
            ulonglong2 yv = *(const ulonglong2*)&buf[j * PAD + 4 * lane];
            float q0, q1, q2, q3;
            UNPACK(q0, q1, yv.x);
            UNPACK(q2, q3, yv.y);
            u64 d0, d1, d2, d3;
            DUP(d0, q0); DUP(d1, q1); DUP(d2, q2); DUP(d3, q3);
            FMA2(ev[0][0], wa.x, d0); FMA2(ev[0][1], wa.x, d1);
            FMA2(ev[0][2], wa.x, d2); FMA2(ev[0][3], wa.x, d3);
            FMA2(ev[1][0], wa.y, d0); FMA2(ev[1][1], wa.y, d1);
            FMA2(ev[1][2], wa.y, d2); FMA2(ev[1][3], wa.y, d3);
        }
        __syncthreads();
        b ^= 1;
    }

    // ---- write un-normalized partials ----
#pragma unroll
    for (int a = 0; a < 2; a++) {
        float e0[4], e1[4];
#pragma unroll
        for (int d = 0; d < 4; d++) UNPACK(e0[d], e1[d], ev[a][d]);
        *(float4*)&g_pev[half][n0 + r0 + 2 * a    ][4 * lane] = make_float4(e0[0], e0[1], e0[2], e0[3]);
        *(float4*)&g_pev[half][n0 + r0 + 2 * a + 1][4 * lane] = make_float4(e1[0], e1[1], e1[2], e1[3]);
    }
    if (lane == 0) {
#pragma unroll
        for (int i = 0; i < 4; i++) {
            g_pm[half][n0 + r0 + i] = mrow[i];
            g_ps[half][n0 + r0 + i] = srow[i];
        }
    }
}

__global__ __launch_bounds__(256) void combine_kernel(
    const float* __restrict__ x, const float* __restrict__ t,
    float* __restrict__ out, int N)
{
    int row  = blockIdx.x * 8 + (threadIdx.x >> 5);
    int lane = threadIdx.x & 31;
    if (row >= N) return;
    float m0 = g_pm[0][row], m1 = g_pm[1][row];
    float s0 = g_ps[0][row], s1 = g_ps[1][row];
    float mxv = fmaxf(m0, m1);
    float a0 = __expf(m0 - mxv), a1 = __expf(m1 - mxv);
    float inv = 1.0f / fmaf(s0, a0, s1 * a1);
    float tt = t[row];
    float lm = -0.25f * tt * tt * (20.0f - 0.1f) - 0.5f * tt * 0.1f;
    float var = fmaxf(1.0f - expf(2.0f * lm), 1e-12f);
    float iv = 1.0f / var;
    float4 e0 = ((const float4*)g_pev[0][row])[lane];
    float4 e1 = ((const float4*)g_pev[1][row])[lane];
    float4 xv = ((const float4*)(x + (size_t)row * DD))[lane];
    float4 o;
    o.x = (fmaf(e0.x, a0, e1.x * a1) * inv - xv.x) * iv;
    o.y = (fmaf(e0.y, a0, e1.y * a1) * inv - xv.y) * iv;
    o.z = (fmaf(e0.z, a0, e1.z * a1) * inv - xv.z) * iv;
    o.w = (fmaf(e0.w, a0, e1.w * a1) * inv - xv.w) * iv;
    ((float4*)(out + (size_t)row * DD))[lane] = o;
}

extern "C" void kernel_launch(void* const* d_in, const int* in_sizes, int n_in,
                              void* d_out, int out_size) {
    const float* x = (const float*)d_in[0];
    const float* t = (const float*)d_in[1];
    const float* y = (const float*)d_in[2];
    float* out = (float*)d_out;
    const int N = in_sizes[1];
    const int M = in_sizes[2] / DD;

    size_t smem = (size_t)(BN * PAD + 2 * BM * PAD + 16 * BM * 4 + 2 * BM + 2 * BN) * sizeof(float);
    cudaFuncSetAttribute(gmm_kernel, cudaFuncAttributeMaxDynamicSharedMemorySize, (int)smem);

    y2_kernel<<<(M + 7) / 8, 256>>>(y, M);
    gmm_kernel<<<dim3(N / BN, 2), THREADS, smem>>>(x, t, y, M);
    combine_kernel<<<(N + 7) / 8, 256>>>(x, t, out, N);
    phase_kernel<<<1, 32>>>();   // 4 launches/call -> ncu -s5 lands on gmm_kernel
}

// round 11
// speedup vs baseline: 1.4761x; 1.0021x over previous
#include <cuda_runtime.h>
#include <cstdint>

#define BN 64
#define BM 128
#define DD 128
#define PAD 132
#define THREADS 512
#define NMAX 4096
#define MMAX 16384
#define SLOTS 2

typedef unsigned long long u64;

__device__ float g_y2[MMAX];
__device__ float g_pev[SLOTS][NMAX][DD];
__device__ float g_pm[SLOTS][NMAX];
__device__ float g_ps[SLOTS][NMAX];

#define FMA2(d,a,b) asm("fma.rn.f32x2 %0,%1,%2,%0;" : "+l"(d) : "l"(a), "l"(b))
#define MUL2(d,a,b) asm("mul.rn.f32x2 %0,%1,%2;" : "=l"(d) : "l"(a), "l"(b))
#define UNPACK(lo,hi,p) asm("mov.b64 {%0,%1},%2;" : "=f"(lo), "=f"(hi) : "l"(p))
#define PACK(d,lo,hi) asm("mov.b64 %0,{%1,%2};" : "=l"(d) : "f"(lo), "f"(hi))
#define DUP(d,v) asm("mov.b64 %0,{%1,%1};" : "=l"(d) : "f"(v))

__global__ __launch_bounds__(256) void y2_kernel(const float* __restrict__ y, int M) {
    int gw   = (blockIdx.x * blockDim.x + threadIdx.x) >> 5;
    int lane = threadIdx.x & 31;
    if (gw >= M) return;
    float4 v = ((const float4*)(y + (size_t)gw * DD))[lane];
    float s = v.x * v.x + v.y * v.y + v.z * v.z + v.w * v.w;
#pragma unroll
    for (int o = 16; o; o >>= 1) s += __shfl_xor_sync(0xffffffffu, s, o);
    if (lane == 0) g_y2[gw] = s;
}

// phase-shift no-op: makes launches-per-call == 4 so ncu (-s 5 -c 1) lands on gmm_kernel
__global__ void phase_kernel() {}

__device__ __forceinline__ void cpa16(float* dst, const float* src) {
    uint32_t s = (uint32_t)__cvta_generic_to_shared(dst);
    asm volatile("cp.async.cg.shared.global [%0], [%1], 16;" :: "r"(s), "l"(src));
}

__global__ __launch_bounds__(THREADS, 1) void gmm_kernel(
    const float* __restrict__ x, const float* __restrict__ t,
    const float* __restrict__ y, int M)
{
    extern __shared__ float sm[];
    float* x_s = sm;                       // BN*PAD (A-scaled x)
    float* y_n = x_s + BN * PAD;           // 2 * BM * PAD
    float* w_s = y_n + 2 * BM * PAD;       // 16 warps * BM * 4 (row-interleaved)
    float* y2s = w_s + 16 * BM * 4;        // 2 * BM
    float* sA  = y2s + 2 * BM;             // BN
    float* sC  = sA + BN;                  // BN

    const int tid  = threadIdx.x;
    const int lane = tid & 31;
    const int w    = tid >> 5;
    const int n0   = blockIdx.x * BN;
    const int half = blockIdx.y;
    const int halfM = M >> 1;
    const float* yg  = y + (size_t)half * halfM * DD;
    const float* y2g = g_y2 + (size_t)half * halfM;
    const int r0 = w * 4;                  // this warp's 4 rows
    float* w_w = w_s + w * (BM * 4);

    if (tid < BN) {
        float tt = t[n0 + tid];
        float lm = -0.25f * tt * tt * (20.0f - 0.1f) - 0.5f * tt * 0.1f;
        float mean = expf(lm);
        float var  = fmaxf(1.0f - expf(2.0f * lm), 1e-12f);
        float iv   = 1.0f / var;
        sA[tid] = iv * mean;
        sC[tid] = -0.5f * iv * mean * mean;
    }
    __syncthreads();

    // stage x pre-scaled by A (logit = <A*x, y> + C*y2)
#pragma unroll
    for (int i = tid; i < BN * DD / 4; i += THREADS) {
        int r = i >> 5, cc = i & 31;
        float4 v = ((const float4*)(x + (size_t)(n0 + r) * DD))[cc];
        float a = sA[r];
        v.x *= a; v.y *= a; v.z *= a; v.w *= a;
        *(float4*)&x_s[r * PAD + 4 * cc] = v;
    }

    float C[4];
#pragma unroll
    for (int i = 0; i < 4; i++) C[i] = sC[r0 + i];

    // ev pairs over row-pairs: ev[rp][d] = (row 2rp, row 2rp+1), d = 4 f32x2 = 8 floats... 
    // per thread output: 4 rows x 8 d-floats held as ev[2 row-pairs][4 packed-d]
    u64 ev[2][4];
#pragma unroll
    for (int a = 0; a < 2; a++)
#pragma unroll
        for (int d = 0; d < 4; d++) ev[a][d] = 0ULL;
    float mrow[4], srow[4];
    const float NEG_INF = __int_as_float(0xff800000);
#pragma unroll
    for (int i = 0; i < 4; i++) { mrow[i] = NEG_INF; srow[i] = 0.0f; }

    auto load_tile = [&](int b, int tile) {
        float* buf = y_n + b * (BM * PAD);
        const float* src = yg + (size_t)tile * BM * DD;
#pragma unroll
        for (int i = tid; i < BM * DD / 4; i += THREADS) {
            int j = i >> 5, cc = i & 31;
            cpa16(&buf[j * PAD + 4 * cc], src + j * DD + 4 * cc);
        }
        if (tid < BM / 4) cpa16(&y2s[b * BM + 4 * tid], y2g + tile * BM + 4 * tid);
        asm volatile("cp.async.commit_group;");
    };

    const int nt = halfM / BM;
    load_tile(0, 0);
    int b = 0;
    for (int it = 0; it < nt; ++it) {
        if (it + 1 < nt) {
            load_tile(b ^ 1, it + 1);
            asm volatile("cp.async.wait_group 1;");
        } else {
            asm volatile("cp.async.wait_group 0;");
        }
        __syncthreads();

        float* buf = y_n + b * (BM * PAD);

        // ---- GEMM1: 4 rows x 4 cols per thread, packed f32x2 over k ----
        u64 acc[4][4];
#pragma unroll
        for (int i = 0; i < 4; i++)
#pragma unroll
            for (int cc = 0; cc < 4; cc++) acc[i][cc] = 0ULL;

#pragma unroll 2
        for (int k = 0; k < DD; k += 4) {
            ulonglong2 yv0 = *(const ulonglong2*)&buf[(lane      ) * PAD + k];
            ulonglong2 yv1 = *(const ulonglong2*)&buf[(lane +  32) * PAD + k];
            ulonglong2 yv2 = *(const ulonglong2*)&buf[(lane +  64) * PAD + k];
            ulonglong2 yv3 = *(const ulonglong2*)&buf[(lane +  96) * PAD + k];
            ulonglong2 xv[4];
#pragma unroll
            for (int i = 0; i < 4; i++)
                xv[i] = *(const ulonglong2*)&x_s[(r0 + i) * PAD + k];
#pragma unroll
            for (int i = 0; i < 4; i++) {
                FMA2(acc[i][0], xv[i].x, yv0.x);
                FMA2(acc[i][1], xv[i].x, yv1.x);
                FMA2(acc[i][2], xv[i].x, yv2.x);
                FMA2(acc[i][3], xv[i].x, yv3.x);
            }
#pragma unroll
            for (int i = 0; i < 4; i++) {
                FMA2(acc[i][0], xv[i].y, yv0.y);
                FMA2(acc[i][1], xv[i].y, yv1.y);
                FMA2(acc[i][2], xv[i].y, yv2.y);
                FMA2(acc[i][3], xv[i].y, yv3.y);
            }
        }

        // ---- logits ----
        float lv[4][4];
#pragma unroll
        for (int i = 0; i < 4; i++)
#pragma unroll
            for (int cc = 0; cc < 4; cc++) {
                float lo, hi; UNPACK(lo, hi, acc[i][cc]);
                lv[i][cc] = lo + hi;
            }
        float y2v[4];
#pragma unroll
        for (int cc = 0; cc < 4; cc++) y2v[cc] = y2s[b * BM + lane + 32 * cc];
#pragma unroll
        for (int i = 0; i < 4; i++)
#pragma unroll
            for (int cc = 0; cc < 4; cc++) lv[i][cc] = fmaf(C[i], y2v[cc], lv[i][cc]);

        // ---- per-warp online softmax (4 row chains) ----
        float mx[4];
#pragma unroll
        for (int i = 0; i < 4; i++)
            mx[i] = fmaxf(fmaxf(lv[i][0], lv[i][1]), fmaxf(lv[i][2], lv[i][3]));
#pragma unroll
        for (int o = 16; o; o >>= 1)
#pragma unroll
            for (int i = 0; i < 4; i++)
                mx[i] = fmaxf(mx[i], __shfl_xor_sync(0xffffffffu, mx[i], o));

        float scl[4], ps[4];
#pragma unroll
        for (int i = 0; i < 4; i++) {
            float mn = fmaxf(mrow[i], mx[i]);
            scl[i] = __expf(mrow[i] - mn);
            mrow[i] = mn;
        }
        float pv[4][4];
#pragma unroll
        for (int i = 0; i < 4; i++) {
#pragma unroll
            for (int cc = 0; cc < 4; cc++) pv[i][cc] = __expf(lv[i][cc] - mrow[i]);
            ps[i] = (pv[i][0] + pv[i][1]) + (pv[i][2] + pv[i][3]);
        }
#pragma unroll
        for (int o = 16; o; o >>= 1)
#pragma unroll
            for (int i = 0; i < 4; i++)
                ps[i] += __shfl_xor_sync(0xffffffffu, ps[i], o);
#pragma unroll
        for (int i = 0; i < 4; i++) srow[i] = fmaf(srow[i], scl[i], ps[i]);

        // rescale ev accumulators (row pairs)
#pragma unroll
        for (int a = 0; a < 2; a++) {
            u64 s2; PACK(s2, scl[2 * a], scl[2 * a + 1]);
#pragma unroll
            for (int d = 0; d < 4; d++) MUL2(ev[a][d], ev[a][d], s2);
        }

        // store weights row-interleaved: w_w[4*j + r] = p[r][j]
#pragma unroll
        for (int cc = 0; cc < 4; cc++) {
            int j = lane + 32 * cc;
            *(float4*)&w_w[4 * j] = make_float4(pv[0][cc], pv[1][cc], pv[2][cc], pv[3][cc]);
        }
        __syncwarp();

        // ---- GEMM2: ev[row-pair][d] += (w_r0,w_r1) * (y_d,y_d) ----
#pragma unroll 4
        for (int j = 0; j < BM; j++) {
            ulonglong2 wa = *(const ulonglong2*)&w_w[4 * j];   // (w_r0,w_r1),(w_r2,w_r3)
            ulonglong2 yv = *(const ulonglong2*)&buf[j * PAD + 4 * lane];
            float q0, q1, q2, q3;
            UNPACK(q0, q1, yv.x);
            UNPACK(q2, q3, yv.y);
            u64 d0, d1, d2, d3;
            DUP(d0, q0); DUP(d1, q1); DUP(d2, q2); DUP(d3, q3);
            FMA2(ev[0][0], wa.x, d0); FMA2(ev[0][1], wa.x, d1);
            FMA2(ev[0][2], wa.x, d2); FMA2(ev[0][3], wa.x, d3);
            FMA2(ev[1][0], wa.y, d0); FMA2(ev[1][1], wa.y, d1);
            FMA2(ev[1][2], wa.y, d2); FMA2(ev[1][3], wa.y, d3);
        }
        __syncthreads();
        b ^= 1;
    }

    // ---- write un-normalized partials ----
#pragma unroll
    for (int a = 0; a < 2; a++) {
        float e0[4], e1[4];
#pragma unroll
        for (int d = 0; d < 4; d++) UNPACK(e0[d], e1[d], ev[a][d]);
        *(float4*)&g_pev[half][n0 + r0 + 2 * a    ][4 * lane] = make_float4(e0[0], e0[1], e0[2], e0[3]);
        *(float4*)&g_pev[half][n0 + r0 + 2 * a + 1][4 * lane] = make_float4(e1[0], e1[1], e1[2], e1[3]);
    }
    if (lane == 0) {
#pragma unroll
        for (int i = 0; i < 4; i++) {
            g_pm[half][n0 + r0 + i] = mrow[i];
            g_ps[half][n0 + r0 + i] = srow[i];
        }
    }
}

__global__ __launch_bounds__(256) void combine_kernel(
    const float* __restrict__ x, const float* __restrict__ t,
    float* __restrict__ out, int N)
{
    int row  = blockIdx.x * 8 + (threadIdx.x >> 5);
    int lane = threadIdx.x & 31;
    if (row >= N) return;
    float m0 = g_pm[0][row], m1 = g_pm[1][row];
    float s0 = g_ps[0][row], s1 = g_ps[1][row];
    float mxv = fmaxf(m0, m1);
    float a0 = __expf(m0 - mxv), a1 = __expf(m1 - mxv);
    float inv = 1.0f / fmaf(s0, a0, s1 * a1);
    float tt = t[row];
    float lm = -0.25f * tt * tt * (20.0f - 0.1f) - 0.5f * tt * 0.1f;
    float var = fmaxf(1.0f - expf(2.0f * lm), 1e-12f);
    float iv = 1.0f / var;
    float4 e0 = ((const float4*)g_pev[0][row])[lane];
    float4 e1 = ((const float4*)g_pev[1][row])[lane];
    float4 xv = ((const float4*)(x + (size_t)row * DD))[lane];
    float4 o;
    o.x = (fmaf(e0.x, a0, e1.x * a1) * inv - xv.x) * iv;
    o.y = (fmaf(e0.y, a0, e1.y * a1) * inv - xv.y) * iv;
    o.z = (fmaf(e0.z, a0, e1.z * a1) * inv - xv.z) * iv;
    o.w = (fmaf(e0.w, a0, e1.w * a1) * inv - xv.w) * iv;
    ((float4*)(out + (size_t)row * DD))[lane] = o;
}

extern "C" void kernel_launch(void* const* d_in, const int* in_sizes, int n_in,
                              void* d_out, int out_size) {
    const float* x = (const float*)d_in[0];
    const float* t = (const float*)d_in[1];
    const float* y = (const float*)d_in[2];
    float* out = (float*)d_out;
    const int N = in_sizes[1];
    const int M = in_sizes[2] / DD;

    size_t smem = (size_t)(BN * PAD + 2 * BM * PAD + 16 * BM * 4 + 2 * BM + 2 * BN) * sizeof(float);
    cudaFuncSetAttribute(gmm_kernel, cudaFuncAttributeMaxDynamicSharedMemorySize, (int)smem);

    y2_kernel<<<(M + 7) / 8, 256>>>(y, M);
    gmm_kernel<<<dim3(N / BN, 2), THREADS, smem>>>(x, t, y, M);
    combine_kernel<<<(N + 7) / 8, 256>>>(x, t, out, N);
    phase_kernel<<<1, 32>>>();   // 4 launches/call -> ncu -s5 lands on gmm_kernel
}

// round 14
// speedup vs baseline: 1.8416x; 1.2476x over previous
#include <cuda_runtime.h>
#include <cstdint>

#define DD 128
#define THREADS 256
#define NMAX 4096
#define MMAX 16384
#define SLOTS 4

typedef unsigned long long u64;

__device__ float g_y2[MMAX];
__device__ float g_pev[SLOTS][NMAX][DD];
__device__ float g_pm[SLOTS][NMAX];
__device__ float g_ps[SLOTS][NMAX];

// ---- smem float offsets ----
#define F_XS   0                    // 128 x 132
#define F_YHI  16896                // 64 x 132 (tf32-rounded hi)
#define F_YLO  25344                // 64 x 132 (tf32 lo)
#define F_WS   33792                // 8 warps x 64 j x 20 (16 rows + pad)
#define F_Y2   44032                // 64
#define F_SA   44096                // 128
#define F_SC   44224                // 128
#define F_SCL  44352                // 8 warps x 16
#define F_TOT  44480                // floats -> 177,920 B

#define FMA2(d,a,b) asm("fma.rn.f32x2 %0,%1,%2,%0;" : "+l"(d) : "l"(a), "l"(b))
#define MUL2(d,a,b) asm("mul.rn.f32x2 %0,%1,%2;" : "=l"(d) : "l"(a), "l"(b))
#define UNPACK(lo,hi,p) asm("mov.b64 {%0,%1},%2;" : "=f"(lo), "=f"(hi) : "l"(p))
#define DUP(d,v) asm("mov.b64 %0,{%1,%1};" : "=l"(d) : "f"(v))

static __device__ __forceinline__ uint32_t tf32_hi(float f) {
    uint32_t u;
    asm("cvt.rna.tf32.f32 %0, %1;" : "=r"(u) : "f"(f));
    return u;
}

// D += A*B, m16n8k8 tf32 (A row-major, B col-major)
#define MMA8(d, a0, a1, a2, a3, b0, b1) \
    asm volatile("mma.sync.aligned.m16n8k8.row.col.f32.tf32.tf32.f32 " \
        "{%0,%1,%2,%3}, {%4,%5,%6,%7}, {%8,%9}, {%0,%1,%2,%3};" \
        : "+f"((d)[0]), "+f"((d)[1]), "+f"((d)[2]), "+f"((d)[3]) \
        : "r"(a0), "r"(a1), "r"(a2), "r"(a3), "r"(b0), "r"(b1))

__global__ __launch_bounds__(256) void y2_kernel(const float* __restrict__ y, int M) {
    int gw   = (blockIdx.x * blockDim.x + threadIdx.x) >> 5;
    int lane = threadIdx.x & 31;
    if (gw >= M) return;
    float4 v = ((const float4*)(y + (size_t)gw * DD))[lane];
    float s = v.x * v.x + v.y * v.y + v.z * v.z + v.w * v.w;
#pragma unroll
    for (int o = 16; o; o >>= 1) s += __shfl_xor_sync(0xffffffffu, s, o);
    if (lane == 0) g_y2[gw] = s;
}

__global__ __launch_bounds__(THREADS, 1) void gmm_kernel(
    const float* __restrict__ x, const float* __restrict__ t,
    const float* __restrict__ y, int M)
{
    extern __shared__ float sm[];
    float* xs   = sm + F_XS;
    float* yhi  = sm + F_YHI;
    float* ylo  = sm + F_YLO;
    float* ws   = sm + F_WS;
    float* y2s  = sm + F_Y2;
    float* sA   = sm + F_SA;
    float* sC   = sm + F_SC;
    float* scls = sm + F_SCL;

    const int tid  = threadIdx.x;
    const int lane = tid & 31;
    const int w    = tid >> 5;
    const int quad = lane >> 2;     // t/4: 0..7
    const int qi   = lane & 3;      // t%4
    const int n0   = blockIdx.x * 128;
    const int q    = blockIdx.y;
    const int mq   = M >> 2;
    const int ybase = q * mq;
    const int nt   = mq >> 6;       // 64 tiles of 64 y-rows

    // per-row VP-SDE constants
    if (tid < 128) {
        float tt = t[n0 + tid];
        float lm = -0.25f * tt * tt * (20.0f - 0.1f) - 0.5f * tt * 0.1f;
        float mean = expf(lm);
        float var  = fmaxf(1.0f - expf(2.0f * lm), 1e-12f);
        float iv   = 1.0f / var;
        sA[tid] = iv * mean;
        sC[tid] = -0.5f * iv * mean * mean;
    }
    __syncthreads();

    // stage A-scaled x: xs[row][132]
#pragma unroll
    for (int i = tid; i < 128 * 32; i += THREADS) {
        int r = i >> 5, c = i & 31;
        float4 v = *(const float4*)(x + (size_t)(n0 + r) * DD + 4 * c);
        float a = sA[r];
        v.x *= a; v.y *= a; v.z *= a; v.w *= a;
        *(float4*)&xs[r * 132 + 4 * c] = v;
    }

    const float C0 = sC[w * 16 + quad];
    const float C1 = sC[w * 16 + quad + 8];
    const float* xr0 = xs + (w * 16 + quad) * 132;
    const float* xr1 = xr0 + 8 * 132;
    float* wsw = ws + w * (64 * 20);

    u64 ev[8][4];
#pragma unroll
    for (int a = 0; a < 8; a++)
#pragma unroll
        for (int d = 0; d < 4; d++) ev[a][d] = 0ULL;
    const float NEG_INF = __int_as_float(0xff800000);
    float m0 = NEG_INF, m1 = NEG_INF, s0 = 0.0f, s1 = 0.0f;
    __syncthreads();

    for (int tile = 0; tile < nt; ++tile) {
        // ---- stage y tile: hi/lo tf32 split + y2 ----
        const float* ysrc = y + (size_t)(ybase + tile * 64) * DD;
#pragma unroll
        for (int i = tid; i < 64 * 32; i += THREADS) {
            int r = i >> 5, c = i & 31;
            float4 v = *(const float4*)(ysrc + (size_t)r * DD + 4 * c);
            float f[4] = {v.x, v.y, v.z, v.w};
            float h[4], l[4];
#pragma unroll
            for (int e = 0; e < 4; e++) {
                h[e] = __uint_as_float(tf32_hi(f[e]));
                l[e] = __uint_as_float(tf32_hi(f[e] - h[e]));
            }
            *(float4*)&yhi[r * 132 + 4 * c] = make_float4(h[0], h[1], h[2], h[3]);
            *(float4*)&ylo[r * 132 + 4 * c] = make_float4(l[0], l[1], l[2], l[3]);
        }
        if (tid < 16) *(float4*)&y2s[4 * tid] = *(const float4*)(g_y2 + ybase + tile * 64 + 4 * tid);
        __syncthreads();

        // ---- GEMM1: logits[16 rows x 64 cols] per warp via m16n8k8 tf32 ----
        float acc[8][4];
#pragma unroll
        for (int nc = 0; nc < 8; nc++)
#pragma unroll
            for (int d = 0; d < 4; d++) acc[nc][d] = 0.0f;

#pragma unroll
        for (int kc = 0; kc < 16; kc++) {
            int k0 = kc * 8;
            float a0f = xr0[k0 + qi],     a1f = xr1[k0 + qi];
            float a2f = xr0[k0 + qi + 4], a3f = xr1[k0 + qi + 4];
            uint32_t ah0 = tf32_hi(a0f), ah1 = tf32_hi(a1f);
            uint32_t ah2 = tf32_hi(a2f), ah3 = tf32_hi(a3f);
            uint32_t al0 = tf32_hi(a0f - __uint_as_float(ah0));
            uint32_t al1 = tf32_hi(a1f - __uint_as_float(ah1));
            uint32_t al2 = tf32_hi(a2f - __uint_as_float(ah2));
            uint32_t al3 = tf32_hi(a3f - __uint_as_float(ah3));
#pragma unroll
            for (int nc = 0; nc < 8; nc++) {
                const float* bh = yhi + (nc * 8 + quad) * 132 + k0 + qi;
                const float* bl = ylo + (nc * 8 + quad) * 132 + k0 + qi;
                uint32_t bh0 = __float_as_uint(bh[0]), bh1 = __float_as_uint(bh[4]);
                uint32_t bl0 = __float_as_uint(bl[0]), bl1 = __float_as_uint(bl[4]);
                MMA8(acc[nc], ah0, ah1, ah2, ah3, bh0, bh1);
                MMA8(acc[nc], ah0, ah1, ah2, ah3, bl0, bl1);
                MMA8(acc[nc], al0, al1, al2, al3, bh0, bh1);
            }
        }

        // ---- logits + online softmax (rows t/4 and t/4+8 of this warp) ----
        float lv[8][4];
        float tm0 = NEG_INF, tm1 = NEG_INF;
#pragma unroll
        for (int nc = 0; nc < 8; nc++) {
            float y2a = y2s[nc * 8 + 2 * qi];
            float y2b = y2s[nc * 8 + 2 * qi + 1];
            lv[nc][0] = fmaf(C0, y2a, acc[nc][0]);
            lv[nc][1] = fmaf(C0, y2b, acc[nc][1]);
            lv[nc][2] = fmaf(C1, y2a, acc[nc][2]);
            lv[nc][3] = fmaf(C1, y2b, acc[nc][3]);
            tm0 = fmaxf(tm0, fmaxf(lv[nc][0], lv[nc][1]));
            tm1 = fmaxf(tm1, fmaxf(lv[nc][2], lv[nc][3]));
        }
#pragma unroll
        for (int o = 1; o <= 2; o <<= 1) {
            tm0 = fmaxf(tm0, __shfl_xor_sync(0xffffffffu, tm0, o));
            tm1 = fmaxf(tm1, __shfl_xor_sync(0xffffffffu, tm1, o));
        }
        float mn0 = fmaxf(m0, tm0), mn1 = fmaxf(m1, tm1);
        float sc0 = __expf(m0 - mn0), sc1 = __expf(m1 - mn1);
        m0 = mn0; m1 = mn1;
        float ts0 = 0.0f, ts1 = 0.0f;
#pragma unroll
        for (int nc = 0; nc < 8; nc++) {
            int j0 = nc * 8 + 2 * qi;
            float w0 = __expf(lv[nc][0] - mn0);
            float w1 = __expf(lv[nc][1] - mn0);
            float w2 = __expf(lv[nc][2] - mn1);
            float w3 = __expf(lv[nc][3] - mn1);
            ts0 += w0 + w1; ts1 += w2 + w3;
            wsw[j0 * 20 + quad]           = w0;
            wsw[j0 * 20 + quad + 8]       = w2;
            wsw[(j0 + 1) * 20 + quad]     = w1;
            wsw[(j0 + 1) * 20 + quad + 8] = w3;
        }
#pragma unroll
        for (int o = 1; o <= 2; o <<= 1) {
            ts0 += __shfl_xor_sync(0xffffffffu, ts0, o);
            ts1 += __shfl_xor_sync(0xffffffffu, ts1, o);
        }
        s0 = fmaf(s0, sc0, ts0);
        s1 = fmaf(s1, sc1, ts1);
        if (qi == 0) {
            scls[w * 16 + quad]     = sc0;
            scls[w * 16 + quad + 8] = sc1;
        }
        __syncwarp();

        // ---- rescale ev ----
#pragma unroll
        for (int a = 0; a < 8; a++) {
            u64 sp = *(const u64*)&scls[w * 16 + 2 * a];
#pragma unroll
            for (int d = 0; d < 4; d++) MUL2(ev[a][d], ev[a][d], sp);
        }

        // ---- GEMM2: ev[rowpair][d] += w * y (fp32 FFMA2) ----
#pragma unroll 2
        for (int j = 0; j < 64; j++) {
            float4 yh4 = *(const float4*)&yhi[j * 132 + 4 * lane];
            float4 yl4 = *(const float4*)&ylo[j * 132 + 4 * lane];
            float q0 = yh4.x + yl4.x, q1 = yh4.y + yl4.y;
            float q2 = yh4.z + yl4.z, q3 = yh4.w + yl4.w;
            u64 d0, d1, d2, d3;
            DUP(d0, q0); DUP(d1, q1); DUP(d2, q2); DUP(d3, q3);
            const ulonglong2 wpA = *(const ulonglong2*)&wsw[j * 20];
            const ulonglong2 wpB = *(const ulonglong2*)&wsw[j * 20 + 4];
            const ulonglong2 wpC = *(const ulonglong2*)&wsw[j * 20 + 8];
            const ulonglong2 wpD = *(const ulonglong2*)&wsw[j * 20 + 12];
            FMA2(ev[0][0], wpA.x, d0); FMA2(ev[0][1], wpA.x, d1);
            FMA2(ev[0][2], wpA.x, d2); FMA2(ev[0][3], wpA.x, d3);
            FMA2(ev[1][0], wpA.y, d0); FMA2(ev[1][1], wpA.y, d1);
            FMA2(ev[1][2], wpA.y, d2); FMA2(ev[1][3], wpA.y, d3);
            FMA2(ev[2][0], wpB.x, d0); FMA2(ev[2][1], wpB.x, d1);
            FMA2(ev[2][2], wpB.x, d2); FMA2(ev[2][3], wpB.x, d3);
            FMA2(ev[3][0], wpB.y, d0); FMA2(ev[3][1], wpB.y, d1);
            FMA2(ev[3][2], wpB.y, d2); FMA2(ev[3][3], wpB.y, d3);
            FMA2(ev[4][0], wpC.x, d0); FMA2(ev[4][1], wpC.x, d1);
            FMA2(ev[4][2], wpC.x, d2); FMA2(ev[4][3], wpC.x, d3);
            FMA2(ev[5][0], wpC.y, d0); FMA2(ev[5][1], wpC.y, d1);
            FMA2(ev[5][2], wpC.y, d2); FMA2(ev[5][3], wpC.y, d3);
            FMA2(ev[6][0], wpD.x, d0); FMA2(ev[6][1], wpD.x, d1);
            FMA2(ev[6][2], wpD.x, d2); FMA2(ev[6][3], wpD.x, d3);
            FMA2(ev[7][0], wpD.y, d0); FMA2(ev[7][1], wpD.y, d1);
            FMA2(ev[7][2], wpD.y, d2); FMA2(ev[7][3], wpD.y, d3);
        }
        __syncthreads();   // y/w buffers reusable next tile
    }

    // ---- write un-normalized partials ----
#pragma unroll
    for (int a = 0; a < 8; a++) {
        float e0[4], e1[4];
#pragma unroll
        for (int d = 0; d < 4; d++) UNPACK(e0[d], e1[d], ev[a][d]);
        *(float4*)&g_pev[q][n0 + w * 16 + 2 * a    ][4 * lane] = make_float4(e0[0], e0[1], e0[2], e0[3]);
        *(float4*)&g_pev[q][n0 + w * 16 + 2 * a + 1][4 * lane] = make_float4(e1[0], e1[1], e1[2], e1[3]);
    }
    if (qi == 0) {
        g_pm[q][n0 + w * 16 + quad]     = m0;
        g_pm[q][n0 + w * 16 + quad + 8] = m1;
        g_ps[q][n0 + w * 16 + quad]     = s0;
        g_ps[q][n0 + w * 16 + quad + 8] = s1;
    }
}

__global__ __launch_bounds__(256) void combine_kernel(
    const float* __restrict__ x, const float* __restrict__ t,
    float* __restrict__ out, int N)
{
    int row  = blockIdx.x * 8 + (threadIdx.x >> 5);
    int lane = threadIdx.x & 31;
    if (row >= N) return;
    const float NEG_INF = __int_as_float(0xff800000);

    float m[SLOTS], s[SLOTS];
#pragma unroll
    for (int k = 0; k < SLOTS; k++) {
        s[k] = g_ps[k][row];
        m[k] = (s[k] > 0.0f) ? g_pm[k][row] : NEG_INF;
    }
    float mxv = m[0];
#pragma unroll
    for (int k = 1; k < SLOTS; k++) mxv = fmaxf(mxv, m[k]);
    float a[SLOTS];
    float denom = 0.0f;
#pragma unroll
    for (int k = 0; k < SLOTS; k++) { a[k] = __expf(m[k] - mxv); denom = fmaf(s[k], a[k], denom); }
    float inv = 1.0f / denom;

    float tt = t[row];
    float lm = -0.25f * tt * tt * (20.0f - 0.1f) - 0.5f * tt * 0.1f;
    float var = fmaxf(1.0f - expf(2.0f * lm), 1e-12f);
    float iv = 1.0f / var;

    float4 acc = make_float4(0.f, 0.f, 0.f, 0.f);
#pragma unroll
    for (int k = 0; k < SLOTS; k++) {
        float4 e = ((const float4*)g_pev[k][row])[lane];
        acc.x = fmaf(e.x, a[k], acc.x);
        acc.y = fmaf(e.y, a[k], acc.y);
        acc.z = fmaf(e.z, a[k], acc.z);
        acc.w = fmaf(e.w, a[k], acc.w);
    }
    float4 xv = ((const float4*)(x + (size_t)row * DD))[lane];
    float4 o;
    o.x = (acc.x * inv - xv.x) * iv;
    o.y = (acc.y * inv - xv.y) * iv;
    o.z = (acc.z * inv - xv.z) * iv;
    o.w = (acc.w * inv - xv.w) * iv;
    ((float4*)(out + (size_t)row * DD))[lane] = o;
}

extern "C" void kernel_launch(void* const* d_in, const int* in_sizes, int n_in,
                              void* d_out, int out_size) {
    const float* x = (const float*)d_in[0];
    const float* t = (const float*)d_in[1];
    const float* y = (const float*)d_in[2];
    float* out = (float*)d_out;
    const int N = in_sizes[1];
    const int M = in_sizes[2] / DD;

    size_t smem = (size_t)F_TOT * sizeof(float);
    cudaFuncSetAttribute(gmm_kernel, cudaFuncAttributeMaxDynamicSharedMemorySize, (int)smem);

    y2_kernel<<<(M + 7) / 8, 256>>>(y, M);
    gmm_kernel<<<dim3(N / 128, 4), THREADS, smem>>>(x, t, y, M);
    combine_kernel<<<(N + 7) / 8, 256>>>(x, t, out, N);
}

// round 15
// speedup vs baseline: 2.3365x; 1.2688x over previous
#include <cuda_runtime.h>
#include <cstdint>

#define DD 128
#define THREADS 256
#define NMAX 4096
#define MMAX 16384
#define SLOTS 4
#define TPT 9216            // floats per transposed tile (128 x 72)

typedef unsigned long long u64;

__device__ float g_y2[MMAX];
__device__ float g_yth[(MMAX / 64) * TPT];
__device__ float g_ytl[(MMAX / 64) * TPT];
__device__ float g_pev[SLOTS][NMAX][DD];
__device__ float g_pm[SLOTS][NMAX];
__device__ float g_ps[SLOTS][NMAX];

static __device__ __forceinline__ uint32_t tf32_hi(float f) {
    uint32_t u;
    asm("cvt.rna.tf32.f32 %0, %1;" : "=r"(u) : "f"(f));
    return u;
}

// D += A*B, m16n8k8 tf32 (A row-major, B col-major) — validated in R13
#define MMA8(d, a0, a1, a2, a3, b0, b1) \
    asm volatile("mma.sync.aligned.m16n8k8.row.col.f32.tf32.tf32.f32 " \
        "{%0,%1,%2,%3}, {%4,%5,%6,%7}, {%8,%9}, {%0,%1,%2,%3};" \
        : "+f"((d)[0]), "+f"((d)[1]), "+f"((d)[2]), "+f"((d)[3]) \
        : "r"(a0), "r"(a1), "r"(a2), "r"(a3), "r"(b0), "r"(b1))

__device__ __forceinline__ void cpa16(float* dst, const float* src) {
    uint32_t s = (uint32_t)__cvta_generic_to_shared(dst);
    asm volatile("cp.async.cg.shared.global [%0], [%1], 16;" :: "r"(s), "l"(src));
}

// ---- prep: per 64-row tile, compute y2 + transposed hi/lo tf32 with j-perm ----
__global__ __launch_bounds__(128) void prep_kernel(const float* __restrict__ y, int M) {
    __shared__ float ys[64 * 129];
    const int t = blockIdx.x;
    const int tid = threadIdx.x;
    const float* src = y + (size_t)t * 64 * DD;

    for (int i = tid; i < 64 * 32; i += 128) {
        int r = i >> 5, c = i & 31;
        float4 v = *(const float4*)(src + (size_t)r * DD + 4 * c);
        ys[r * 129 + 4 * c + 0] = v.x;
        ys[r * 129 + 4 * c + 1] = v.y;
        ys[r * 129 + 4 * c + 2] = v.z;
        ys[r * 129 + 4 * c + 3] = v.w;
    }
    __syncthreads();

    if (tid < 64) {
        float s = 0.0f;
        for (int k = 0; k < DD; k++) { float v = ys[tid * 129 + k]; s = fmaf(v, v, s); }
        g_y2[t * 64 + tid] = s;
    }

    float* dh = g_yth + (size_t)t * TPT;
    float* dl = g_ytl + (size_t)t * TPT;
    for (int i = tid; i < TPT; i += 128) {
        int d = i / 72, p = i % 72;
        int a = p / 18, bb = p % 18;
        float hi = 0.0f, lo = 0.0f;
        if (bb < 16) {
            int j = 4 * bb + a;
            float v = ys[j * 129 + d];
            hi = __uint_as_float(tf32_hi(v));
            lo = __uint_as_float(tf32_hi(v - hi));
        }
        dh[i] = hi;
        dl[i] = lo;
    }
}

// ---- main: both GEMMs on mma.sync tf32 ----
__global__ __launch_bounds__(THREADS, 1) void gmm_kernel(
    const float* __restrict__ x, const float* __restrict__ t, int M)
{
    extern __shared__ float sm[];
    // [buf][hi/lo][9216] y tiles; then ws [hl][8 warps][1280]; then y2 [2][64]
    float* wsb = sm + 4 * TPT;           // 36864
    float* y2s = wsb + 2 * 8 * 1280;     // +20480 = 57344; total 57472 floats

    const int tid  = threadIdx.x;
    const int lane = tid & 31;
    const int w    = tid >> 5;
    const int quad = lane >> 2;
    const int qi   = lane & 3;
    const int n0   = blockIdx.x * 128;
    const int q    = blockIdx.y;
    const int nt   = (M >> 2) >> 6;          // tiles per quarter (64)
    const int tg0  = q * nt;

    // per-thread row constants (rows r0=quad, r1=quad+8 of this warp's 16)
    const int row0 = n0 + w * 16 + quad;
    float C0, C1, m0, m1;
    {
        float tt0 = t[row0], tt1 = t[row0 + 8];
        float lm0 = -0.25f * tt0 * tt0 * 19.9f - 0.05f * tt0;
        float lm1 = -0.25f * tt1 * tt1 * 19.9f - 0.05f * tt1;
        float me0 = expf(lm0), me1 = expf(lm1);
        float iv0 = 1.0f / fmaxf(1.0f - expf(2.0f * lm0), 1e-12f);
        float iv1 = 1.0f / fmaxf(1.0f - expf(2.0f * lm1), 1e-12f);
        float A0 = iv0 * me0, A1 = iv1 * me1;
        C0 = -0.5f * iv0 * me0 * me0;
        C1 = -0.5f * iv1 * me1 * me1;
        m0 = A0; m1 = A1;                    // stash A in m0/m1 temporarily
    }
    const float A0 = m0, A1 = m1;

    // x A-fragments, A-prescaled, fp32 in regs: xa[row 0/1][2*kc + s], k = 8kc+qi+4s
    float xa[2][32];
#pragma unroll
    for (int kc = 0; kc < 16; kc++) {
        xa[0][2 * kc]     = x[(size_t)row0 * DD + 8 * kc + qi] * A0;
        xa[0][2 * kc + 1] = x[(size_t)row0 * DD + 8 * kc + qi + 4] * A0;
        xa[1][2 * kc]     = x[(size_t)(row0 + 8) * DD + 8 * kc + qi] * A1;
        xa[1][2 * kc + 1] = x[(size_t)(row0 + 8) * DD + 8 * kc + qi + 4] * A1;
    }

    float ev[16][4];
#pragma unroll
    for (int nc = 0; nc < 16; nc++)
#pragma unroll
        for (int d = 0; d < 4; d++) ev[nc][d] = 0.0f;
    const float NEG_INF = __int_as_float(0xff800000);
    m0 = NEG_INF; m1 = NEG_INF;
    float s0 = 0.0f, s1 = 0.0f;

    float* wsh = wsb + w * 1280;
    float* wsl = wsb + 8 * 1280 + w * 1280;
    const int qv = 18 * (quad & 3) + (quad >> 2);

    auto load_tile = [&](int b, int tg) {
        const float* sh = g_yth + (size_t)tg * TPT;
        const float* sl = g_ytl + (size_t)tg * TPT;
        float* dh = sm + (b * 2) * TPT;
        float* dl = sm + (b * 2 + 1) * TPT;
        for (int i = tid; i < TPT / 4; i += THREADS) {
            cpa16(dh + 4 * i, sh + 4 * i);
            cpa16(dl + 4 * i, sl + 4 * i);
        }
        if (tid < 16) cpa16(&y2s[b * 64 + 4 * tid], g_y2 + tg * 64 + 4 * tid);
        asm volatile("cp.async.commit_group;");
    };

    load_tile(0, tg0);
    int b = 0;
    for (int tile = 0; tile < nt; ++tile) {
        if (tile + 1 < nt) {
            load_tile(b ^ 1, tg0 + tile + 1);
            asm volatile("cp.async.wait_group 1;");
        } else {
            asm volatile("cp.async.wait_group 0;");
        }
        __syncthreads();

        const float* ybh = sm + (b * 2) * TPT;
        const float* ybl = sm + (b * 2 + 1) * TPT;

        // ---- GEMM1: logits[16 x 64] per warp ----
        float acc[8][4];
#pragma unroll
        for (int nc = 0; nc < 8; nc++)
#pragma unroll
            for (int d = 0; d < 4; d++) acc[nc][d] = 0.0f;

#pragma unroll
        for (int kc = 0; kc < 16; kc++) {
            float a0f = xa[0][2 * kc], a1f = xa[1][2 * kc];
            float a2f = xa[0][2 * kc + 1], a3f = xa[1][2 * kc + 1];
            uint32_t ah0 = tf32_hi(a0f), ah1 = tf32_hi(a1f);
            uint32_t ah2 = tf32_hi(a2f), ah3 = tf32_hi(a3f);
            uint32_t al0 = tf32_hi(a0f - __uint_as_float(ah0));
            uint32_t al1 = tf32_hi(a1f - __uint_as_float(ah1));
            uint32_t al2 = tf32_hi(a2f - __uint_as_float(ah2));
            uint32_t al3 = tf32_hi(a3f - __uint_as_float(ah3));
            int ro0 = (8 * kc + qi) * 72;
            int ro4 = ro0 + 4 * 72;
#pragma unroll
            for (int nc = 0; nc < 8; nc++) {
                uint32_t bh0 = __float_as_uint(ybh[ro0 + qv + 2 * nc]);
                uint32_t bh1 = __float_as_uint(ybh[ro4 + qv + 2 * nc]);
                uint32_t bl0 = __float_as_uint(ybl[ro0 + qv + 2 * nc]);
                uint32_t bl1 = __float_as_uint(ybl[ro4 + qv + 2 * nc]);
                MMA8(acc[nc], ah0, ah1, ah2, ah3, bh0, bh1);
                MMA8(acc[nc], ah0, ah1, ah2, ah3, bl0, bl1);
                MMA8(acc[nc], al0, al1, al2, al3, bh0, bh1);
            }
        }

        // ---- softmax (rows quad, quad+8) ----
        float lv[8][4];
        float tm0 = NEG_INF, tm1 = NEG_INF;
#pragma unroll
        for (int nc = 0; nc < 8; nc++) {
            float y2a = y2s[b * 64 + nc * 8 + 2 * qi];
            float y2b = y2s[b * 64 + nc * 8 + 2 * qi + 1];
            lv[nc][0] = fmaf(C0, y2a, acc[nc][0]);
            lv[nc][1] = fmaf(C0, y2b, acc[nc][1]);
            lv[nc][2] = fmaf(C1, y2a, acc[nc][2]);
            lv[nc][3] = fmaf(C1, y2b, acc[nc][3]);
            tm0 = fmaxf(tm0, fmaxf(lv[nc][0], lv[nc][1]));
            tm1 = fmaxf(tm1, fmaxf(lv[nc][2], lv[nc][3]));
        }
#pragma unroll
        for (int o = 1; o <= 2; o <<= 1) {
            tm0 = fmaxf(tm0, __shfl_xor_sync(0xffffffffu, tm0, o));
            tm1 = fmaxf(tm1, __shfl_xor_sync(0xffffffffu, tm1, o));
        }
        float mn0 = fmaxf(m0, tm0), mn1 = fmaxf(m1, tm1);
        float sc0 = __expf(m0 - mn0), sc1 = __expf(m1 - mn1);
        m0 = mn0; m1 = mn1;
        float ts0 = 0.0f, ts1 = 0.0f;
#pragma unroll
        for (int nc = 0; nc < 8; nc++) {
            int j0 = nc * 8 + 2 * qi;
            float w00 = __expf(lv[nc][0] - mn0);
            float w01 = __expf(lv[nc][1] - mn0);
            float w10 = __expf(lv[nc][2] - mn1);
            float w11 = __expf(lv[nc][3] - mn1);
            float h00 = __uint_as_float(tf32_hi(w00));
            float h01 = __uint_as_float(tf32_hi(w01));
            float h10 = __uint_as_float(tf32_hi(w10));
            float h11 = __uint_as_float(tf32_hi(w11));
            float l00 = __uint_as_float(tf32_hi(w00 - h00));
            float l01 = __uint_as_float(tf32_hi(w01 - h01));
            float l10 = __uint_as_float(tf32_hi(w10 - h10));
            float l11 = __uint_as_float(tf32_hi(w11 - h11));
            ts0 += (h00 + l00) + (h01 + l01);
            ts1 += (h10 + l10) + (h11 + l11);
            wsh[j0 * 20 + quad]           = h00;
            wsh[j0 * 20 + quad + 8]       = h10;
            wsh[(j0 + 1) * 20 + quad]     = h01;
            wsh[(j0 + 1) * 20 + quad + 8] = h11;
            wsl[j0 * 20 + quad]           = l00;
            wsl[j0 * 20 + quad + 8]       = l10;
            wsl[(j0 + 1) * 20 + quad]     = l01;
            wsl[(j0 + 1) * 20 + quad + 8] = l11;
        }
#pragma unroll
        for (int o = 1; o <= 2; o <<= 1) {
            ts0 += __shfl_xor_sync(0xffffffffu, ts0, o);
            ts1 += __shfl_xor_sync(0xffffffffu, ts1, o);
        }
        s0 = fmaf(s0, sc0, ts0);
        s1 = fmaf(s1, sc1, ts1);

        // rescale evals D-frags (per-thread: rows match softmax rows)
#pragma unroll
        for (int nc = 0; nc < 16; nc++) {
            ev[nc][0] *= sc0; ev[nc][1] *= sc0;
            ev[nc][2] *= sc1; ev[nc][3] *= sc1;
        }
        __syncwarp();

        // ---- GEMM2: evals[16 x 128] += w[16 x 64] @ yT, 3 products ----
#pragma unroll
        for (int jc = 0; jc < 8; jc++) {
            int jb0 = (8 * jc + qi) * 20, jb4 = (8 * jc + qi + 4) * 20;
            uint32_t wh0 = __float_as_uint(wsh[jb0 + quad]);
            uint32_t wh1 = __float_as_uint(wsh[jb0 + quad + 8]);
            uint32_t wh2 = __float_as_uint(wsh[jb4 + quad]);
            uint32_t wh3 = __float_as_uint(wsh[jb4 + quad + 8]);
            uint32_t wl0 = __float_as_uint(wsl[jb0 + quad]);
            uint32_t wl1 = __float_as_uint(wsl[jb0 + quad + 8]);
            uint32_t wl2 = __float_as_uint(wsl[jb4 + quad]);
            uint32_t wl3 = __float_as_uint(wsl[jb4 + quad + 8]);
            int pj = 18 * qi + 2 * jc;
#pragma unroll
            for (int nc = 0; nc < 16; nc++) {
                float2 bh = *(const float2*)&ybh[(8 * nc + quad) * 72 + pj];
                float2 bl = *(const float2*)&ybl[(8 * nc + quad) * 72 + pj];
                uint32_t bh0 = __float_as_uint(bh.x), bh1 = __float_as_uint(bh.y);
                uint32_t bl0 = __float_as_uint(bl.x), bl1 = __float_as_uint(bl.y);
                MMA8(ev[nc], wh0, wh1, wh2, wh3, bh0, bh1);
                MMA8(ev[nc], wh0, wh1, wh2, wh3, bl0, bl1);
                MMA8(ev[nc], wl0, wl1, wl2, wl3, bh0, bh1);
            }
        }
        __syncthreads();
        b ^= 1;
    }

    // ---- write un-normalized partials ----
#pragma unroll
    for (int nc = 0; nc < 16; nc++) {
        int col = nc * 8 + 2 * qi;
        *(float2*)&g_pev[q][row0][col]     = make_float2(ev[nc][0], ev[nc][1]);
        *(float2*)&g_pev[q][row0 + 8][col] = make_float2(ev[nc][2], ev[nc][3]);
    }
    if (qi == 0) {
        g_pm[q][row0] = m0;  g_pm[q][row0 + 8] = m1;
        g_ps[q][row0] = s0;  g_ps[q][row0 + 8] = s1;
    }
}

__global__ __launch_bounds__(256) void combine_kernel(
    const float* __restrict__ x, const float* __restrict__ t,
    float* __restrict__ out, int N)
{
    int row  = blockIdx.x * 8 + (threadIdx.x >> 5);
    int lane = threadIdx.x & 31;
    if (row >= N) return;
    const float NEG_INF = __int_as_float(0xff800000);

    float m[SLOTS], s[SLOTS];
#pragma unroll
    for (int k = 0; k < SLOTS; k++) {
        s[k] = g_ps[k][row];
        m[k] = (s[k] > 0.0f) ? g_pm[k][row] : NEG_INF;
    }
    float mxv = m[0];
#pragma unroll
    for (int k = 1; k < SLOTS; k++) mxv = fmaxf(mxv, m[k]);
    float a[SLOTS];
    float denom = 0.0f;
#pragma unroll
    for (int k = 0; k < SLOTS; k++) { a[k] = __expf(m[k] - mxv); denom = fmaf(s[k], a[k], denom); }
    float inv = 1.0f / denom;

    float tt = t[row];
    float lm = -0.25f * tt * tt * 19.9f - 0.05f * tt;
    float var = fmaxf(1.0f - expf(2.0f * lm), 1e-12f);
    float iv = 1.0f / var;

    float4 acc = make_float4(0.f, 0.f, 0.f, 0.f);
#pragma unroll
    for (int k = 0; k < SLOTS; k++) {
        float4 e = ((const float4*)g_pev[k][row])[lane];
        acc.x = fmaf(e.x, a[k], acc.x);
        acc.y = fmaf(e.y, a[k], acc.y);
        acc.z = fmaf(e.z, a[k], acc.z);
        acc.w = fmaf(e.w, a[k], acc.w);
    }
    float4 xv = ((const float4*)(x + (size_t)row * DD))[lane];
    float4 o;
    o.x = (acc.x * inv - xv.x) * iv;
    o.y = (acc.y * inv - xv.y) * iv;
    o.z = (acc.z * inv - xv.z) * iv;
    o.w = (acc.w * inv - xv.w) * iv;
    ((float4*)(out + (size_t)row * DD))[lane] = o;
}

extern "C" void kernel_launch(void* const* d_in, const int* in_sizes, int n_in,
                              void* d_out, int out_size) {
    const float* x = (const float*)d_in[0];
    const float* t = (const float*)d_in[1];
    const float* y = (const float*)d_in[2];
    float* out = (float*)d_out;
    const int N = in_sizes[1];
    const int M = in_sizes[2] / DD;

    size_t smem = (size_t)(4 * TPT + 2 * 8 * 1280 + 128) * sizeof(float);  // 229,888 B
    cudaFuncSetAttribute(gmm_kernel, cudaFuncAttributeMaxDynamicSharedMemorySize, (int)smem);

    prep_kernel<<<M / 64, 128>>>(y, M);
    gmm_kernel<<<dim3(N / 128, 4), THREADS, smem>>>(x, t, M);
    combine_kernel<<<(N + 7) / 8, 256>>>(x, t, out, N);
}

// round 16
// speedup vs baseline: 5.1565x; 2.2069x over previous
#include <cuda_runtime.h>
#include <cuda_fp16.h>
#include <cstdint>

#define DD 128
#define THREADS 256
#define NMAX 4096
#define MMAX 16384
#define SLOTS 4

// per-tile packed-half2 layouts (word = uint32 = half2)
#define G1W 4352            // 64 rows x 68 words (64 data + 4 pad)
#define G2W 4608            // 128 rows x 36 words (32 data + 4 pad)
#define W_G1H 0
#define W_G1L 4352
#define W_G2H 8704
#define W_G2L 13312
#define W_BUF 17920         // words per buffer

typedef unsigned long long u64;

__device__ float g_y2[MMAX];
__device__ uint32_t g_g1h[(MMAX / 64) * G1W];
__device__ uint32_t g_g1l[(MMAX / 64) * G1W];
__device__ uint32_t g_g2h[(MMAX / 64) * G2W];
__device__ uint32_t g_g2l[(MMAX / 64) * G2W];
__device__ float g_pev[SLOTS][NMAX][DD];
__device__ float g_pm[SLOTS][NMAX];
__device__ float g_ps[SLOTS][NMAX];

static __device__ __forceinline__ uint32_t packh2(__half a, __half b) {
    __half2 h = __halves2half2(a, b);
    return *(uint32_t*)&h;
}
static __device__ __forceinline__ void split2(float a, float b, uint32_t& h, uint32_t& l) {
    __half ha = __float2half_rn(a), hb = __float2half_rn(b);
    __half la = __float2half_rn(a - __half2float(ha));
    __half lb = __float2half_rn(b - __half2float(hb));
    h = packh2(ha, hb);
    l = packh2(la, lb);
}

// D += A*B, m16n8k16 fp16 inputs, fp32 accum (A row-major, B col-major)
#define MMAH(d, a0, a1, a2, a3, b0, b1) \
    asm volatile("mma.sync.aligned.m16n8k16.row.col.f32.f16.f16.f32 " \
        "{%0,%1,%2,%3}, {%4,%5,%6,%7}, {%8,%9}, {%0,%1,%2,%3};" \
        : "+f"((d)[0]), "+f"((d)[1]), "+f"((d)[2]), "+f"((d)[3]) \
        : "r"(a0), "r"(a1), "r"(a2), "r"(a3), "r"(b0), "r"(b1))

__device__ __forceinline__ void cpa16(void* dst, const void* src) {
    uint32_t s = (uint32_t)__cvta_generic_to_shared(dst);
    asm volatile("cp.async.cg.shared.global [%0], [%1], 16;" :: "r"(s), "l"(src));
}

// ---- prep: per 64-row tile -> y2 + two packed-half2 hi/lo layouts ----
__global__ __launch_bounds__(256) void prep_kernel(const float* __restrict__ y) {
    __shared__ float ys[64 * 129];
    const int t = blockIdx.x;
    const int tid = threadIdx.x;
    const float* src = y + (size_t)t * 64 * DD;

    for (int i = tid; i < 64 * 32; i += 256) {
        int r = i >> 5, c = i & 31;
        float4 v = *(const float4*)(src + (size_t)r * DD + 4 * c);
        ys[r * 129 + 4 * c + 0] = v.x;
        ys[r * 129 + 4 * c + 1] = v.y;
        ys[r * 129 + 4 * c + 2] = v.z;
        ys[r * 129 + 4 * c + 3] = v.w;
    }
    __syncthreads();

    if (tid < 64) {
        float s = 0.0f;
        for (int k = 0; k < DD; k++) { float v = ys[tid * 129 + k]; s = fmaf(v, v, s); }
        g_y2[t * 64 + tid] = s;
    }

    // GEMM1 B: rows j (64), pairs along d: word p = d/2 (stride 68)
    uint32_t* d1h = g_g1h + (size_t)t * G1W;
    uint32_t* d1l = g_g1l + (size_t)t * G1W;
    for (int i = tid; i < G1W; i += 256) {
        int j = i / 68, p = i % 68;
        uint32_t h = 0, l = 0;
        if (p < 64) split2(ys[j * 129 + 2 * p], ys[j * 129 + 2 * p + 1], h, l);
        d1h[i] = h; d1l[i] = l;
    }
    // GEMM2 B: rows d (128), pairs along j: word p = j/2 (stride 36)
    uint32_t* d2h = g_g2h + (size_t)t * G2W;
    uint32_t* d2l = g_g2l + (size_t)t * G2W;
    for (int i = tid; i < G2W; i += 256) {
        int d = i / 36, p = i % 36;
        uint32_t h = 0, l = 0;
        if (p < 32) split2(ys[(2 * p) * 129 + d], ys[(2 * p + 1) * 129 + d], h, l);
        d2h[i] = h; d2l[i] = l;
    }
}

__global__ __launch_bounds__(THREADS, 1) void gmm_kernel(
    const float* __restrict__ x, const float* __restrict__ t, int M)
{
    extern __shared__ uint32_t smu[];
    float* y2s = (float*)(smu + 2 * W_BUF);      // 2 x 64

    const int tid  = threadIdx.x;
    const int lane = tid & 31;
    const int w    = tid >> 5;
    const int quad = lane >> 2;
    const int qi   = lane & 3;
    const int n0   = blockIdx.x * 128;
    const int q    = blockIdx.y;
    const int nt   = (M >> 2) >> 6;
    const int tg0  = q * nt;
    const int row0 = n0 + w * 16 + quad;

    float C0, C1, A0, A1;
    {
        float tt0 = t[row0], tt1 = t[row0 + 8];
        float lm0 = -0.25f * tt0 * tt0 * 19.9f - 0.05f * tt0;
        float lm1 = -0.25f * tt1 * tt1 * 19.9f - 0.05f * tt1;
        float me0 = expf(lm0), me1 = expf(lm1);
        float iv0 = 1.0f / fmaxf(1.0f - expf(2.0f * lm0), 1e-12f);
        float iv1 = 1.0f / fmaxf(1.0f - expf(2.0f * lm1), 1e-12f);
        A0 = iv0 * me0; A1 = iv1 * me1;
        C0 = -0.5f * iv0 * me0 * me0;
        C1 = -0.5f * iv1 * me1 * me1;
    }

    // x A-fragments (A-prescaled, fp16 hi/lo packed), resident in regs
    uint32_t ah[8][4], al[8][4];
#pragma unroll
    for (int kc = 0; kc < 8; kc++) {
        int k0 = 16 * kc + 2 * qi;
        const float* x0 = x + (size_t)row0 * DD;
        const float* x1 = x + (size_t)(row0 + 8) * DD;
        split2(x0[k0] * A0,     x0[k0 + 1] * A0, ah[kc][0], al[kc][0]);
        split2(x1[k0] * A1,     x1[k0 + 1] * A1, ah[kc][1], al[kc][1]);
        split2(x0[k0 + 8] * A0, x0[k0 + 9] * A0, ah[kc][2], al[kc][2]);
        split2(x1[k0 + 8] * A1, x1[k0 + 9] * A1, ah[kc][3], al[kc][3]);
    }

    float ev[16][4];
#pragma unroll
    for (int nc = 0; nc < 16; nc++)
#pragma unroll
        for (int d = 0; d < 4; d++) ev[nc][d] = 0.0f;
    const float NEG_INF = __int_as_float(0xff800000);
    float m0 = NEG_INF, m1 = NEG_INF, s0 = 0.0f, s1 = 0.0f;

    auto load_tile = [&](int b, int tg) {
        uint32_t* dst = smu + b * W_BUF;
        const uint32_t* s1h = g_g1h + (size_t)tg * G1W;
        const uint32_t* s1l = g_g1l + (size_t)tg * G1W;
        const uint32_t* s2h = g_g2h + (size_t)tg * G2W;
        const uint32_t* s2l = g_g2l + (size_t)tg * G2W;
        for (int i = tid; i < G1W / 4; i += THREADS) {
            cpa16(dst + W_G1H + 4 * i, s1h + 4 * i);
            cpa16(dst + W_G1L + 4 * i, s1l + 4 * i);
        }
        for (int i = tid; i < G2W / 4; i += THREADS) {
            cpa16(dst + W_G2H + 4 * i, s2h + 4 * i);
            cpa16(dst + W_G2L + 4 * i, s2l + 4 * i);
        }
        if (tid < 16) cpa16(&y2s[b * 64 + 4 * tid], g_y2 + tg * 64 + 4 * tid);
        asm volatile("cp.async.commit_group;");
    };

    load_tile(0, tg0);
    int b = 0;
    for (int tile = 0; tile < nt; ++tile) {
        if (tile + 1 < nt) {
            load_tile(b ^ 1, tg0 + tile + 1);
            asm volatile("cp.async.wait_group 1;");
        } else {
            asm volatile("cp.async.wait_group 0;");
        }
        __syncthreads();

        const uint32_t* b1h = smu + b * W_BUF + W_G1H;
        const uint32_t* b1l = smu + b * W_BUF + W_G1L;
        const uint32_t* b2h = smu + b * W_BUF + W_G2H;
        const uint32_t* b2l = smu + b * W_BUF + W_G2L;

        // ---- GEMM1: logits[16 x 64], 3 fp16 products ----
        float acc[8][4];
#pragma unroll
        for (int nc = 0; nc < 8; nc++)
#pragma unroll
            for (int d = 0; d < 4; d++) acc[nc][d] = 0.0f;

#pragma unroll
        for (int kc = 0; kc < 8; kc++) {
#pragma unroll
            for (int nc = 0; nc < 8; nc++) {
                int base = (8 * nc + quad) * 68 + 8 * kc + qi;
                uint32_t bh0 = b1h[base], bh1 = b1h[base + 4];
                uint32_t bl0 = b1l[base], bl1 = b1l[base + 4];
                MMAH(acc[nc], ah[kc][0], ah[kc][1], ah[kc][2], ah[kc][3], bh0, bh1);
                MMAH(acc[nc], ah[kc][0], ah[kc][1], ah[kc][2], ah[kc][3], bl0, bl1);
                MMAH(acc[nc], al[kc][0], al[kc][1], al[kc][2], al[kc][3], bh0, bh1);
            }
        }

        // ---- softmax (rows quad, quad+8; cols j = 8nc+2qi+{0,1}) ----
        float lv[8][4];
        float tm0 = NEG_INF, tm1 = NEG_INF;
#pragma unroll
        for (int nc = 0; nc < 8; nc++) {
            float y2a = y2s[b * 64 + nc * 8 + 2 * qi];
            float y2b = y2s[b * 64 + nc * 8 + 2 * qi + 1];
            lv[nc][0] = fmaf(C0, y2a, acc[nc][0]);
            lv[nc][1] = fmaf(C0, y2b, acc[nc][1]);
            lv[nc][2] = fmaf(C1, y2a, acc[nc][2]);
            lv[nc][3] = fmaf(C1, y2b, acc[nc][3]);
            tm0 = fmaxf(tm0, fmaxf(lv[nc][0], lv[nc][1]));
            tm1 = fmaxf(tm1, fmaxf(lv[nc][2], lv[nc][3]));
        }
#pragma unroll
        for (int o = 1; o <= 2; o <<= 1) {
            tm0 = fmaxf(tm0, __shfl_xor_sync(0xffffffffu, tm0, o));
            tm1 = fmaxf(tm1, __shfl_xor_sync(0xffffffffu, tm1, o));
        }
        float mn0 = fmaxf(m0, tm0), mn1 = fmaxf(m1, tm1);
        float sc0 = __expf(m0 - mn0), sc1 = __expf(m1 - mn1);
        m0 = mn0; m1 = mn1;

        uint32_t wA[8], wB[8];
        float ts0 = 0.0f, ts1 = 0.0f;
#pragma unroll
        for (int nc = 0; nc < 8; nc++) {
            __half h00 = __float2half_rn(__expf(lv[nc][0] - mn0));
            __half h01 = __float2half_rn(__expf(lv[nc][1] - mn0));
            __half h10 = __float2half_rn(__expf(lv[nc][2] - mn1));
            __half h11 = __float2half_rn(__expf(lv[nc][3] - mn1));
            wA[nc] = packh2(h00, h01);
            wB[nc] = packh2(h10, h11);
            ts0 += __half2float(h00) + __half2float(h01);   // sum the ROUNDED weights
            ts1 += __half2float(h10) + __half2float(h11);
        }
#pragma unroll
        for (int o = 1; o <= 2; o <<= 1) {
            ts0 += __shfl_xor_sync(0xffffffffu, ts0, o);
            ts1 += __shfl_xor_sync(0xffffffffu, ts1, o);
        }
        s0 = fmaf(s0, sc0, ts0);
        s1 = fmaf(s1, sc1, ts1);

#pragma unroll
        for (int nc = 0; nc < 16; nc++) {
            ev[nc][0] *= sc0; ev[nc][1] *= sc0;
            ev[nc][2] *= sc1; ev[nc][3] *= sc1;
        }

        // ---- GEMM2: evals += w @ yT; A-frags straight from D-frag registers ----
#pragma unroll
        for (int jc = 0; jc < 4; jc++) {
            uint32_t a0 = wA[2 * jc], a2 = wA[2 * jc + 1];
            uint32_t a1 = wB[2 * jc], a3 = wB[2 * jc + 1];
#pragma unroll
            for (int nc = 0; nc < 16; nc++) {
                int base = (8 * nc + quad) * 36 + 8 * jc + qi;
                uint32_t bh0 = b2h[base], bh1 = b2h[base + 4];
                uint32_t bl0 = b2l[base], bl1 = b2l[base + 4];
                MMAH(ev[nc], a0, a1, a2, a3, bh0, bh1);
                MMAH(ev[nc], a0, a1, a2, a3, bl0, bl1);
            }
        }
        __syncthreads();
        b ^= 1;
    }

    // ---- write un-normalized partials ----
#pragma unroll
    for (int nc = 0; nc < 16; nc++) {
        int col = nc * 8 + 2 * qi;
        *(float2*)&g_pev[q][row0][col]     = make_float2(ev[nc][0], ev[nc][1]);
        *(float2*)&g_pev[q][row0 + 8][col] = make_float2(ev[nc][2], ev[nc][3]);
    }
    if (qi == 0) {
        g_pm[q][row0] = m0;  g_pm[q][row0 + 8] = m1;
        g_ps[q][row0] = s0;  g_ps[q][row0 + 8] = s1;
    }
}

__global__ __launch_bounds__(256) void combine_kernel(
    const float* __restrict__ x, const float* __restrict__ t,
    float* __restrict__ out, int N)
{
    int row  = blockIdx.x * 8 + (threadIdx.x >> 5);
    int lane = threadIdx.x & 31;
    if (row >= N) return;
    const float NEG_INF = __int_as_float(0xff800000);

    float m[SLOTS], s[SLOTS];
#pragma unroll
    for (int k = 0; k < SLOTS; k++) {
        s[k] = g_ps[k][row];
        m[k] = (s[k] > 0.0f) ? g_pm[k][row] : NEG_INF;
    }
    float mxv = m[0];
#pragma unroll
    for (int k = 1; k < SLOTS; k++) mxv = fmaxf(mxv, m[k]);
    float a[SLOTS];
    float denom = 0.0f;
#pragma unroll
    for (int k = 0; k < SLOTS; k++) { a[k] = __expf(m[k] - mxv); denom = fmaf(s[k], a[k], denom); }
    float inv = 1.0f / denom;

    float tt = t[row];
    float lm = -0.25f * tt * tt * 19.9f - 0.05f * tt;
    float var = fmaxf(1.0f - expf(2.0f * lm), 1e-12f);
    float iv = 1.0f / var;

    float4 acc = make_float4(0.f, 0.f, 0.f, 0.f);
#pragma unroll
    for (int k = 0; k < SLOTS; k++) {
        float4 e = ((const float4*)g_pev[k][row])[lane];
        acc.x = fmaf(e.x, a[k], acc.x);
        acc.y = fmaf(e.y, a[k], acc.y);
        acc.z = fmaf(e.z, a[k], acc.z);
        acc.w = fmaf(e.w, a[k], acc.w);
    }
    float4 xv = ((const float4*)(x + (size_t)row * DD))[lane];
    float4 o;
    o.x = (acc.x * inv - xv.x) * iv;
    o.y = (acc.y * inv - xv.y) * iv;
    o.z = (acc.z * inv - xv.z) * iv;
    o.w = (acc.w * inv - xv.w) * iv;
    ((float4*)(out + (size_t)row * DD))[lane] = o;
}

extern "C" void kernel_launch(void* const* d_in, const int* in_sizes, int n_in,
                              void* d_out, int out_size) {
    const float* x = (const float*)d_in[0];
    const float* t = (const float*)d_in[1];
    const float* y = (const float*)d_in[2];
    float* out = (float*)d_out;
    const int N = in_sizes[1];
    const int M = in_sizes[2] / DD;

    size_t smem = (size_t)(2 * W_BUF) * 4 + 2 * 64 * sizeof(float);   // 143,872 B
    cudaFuncSetAttribute(gmm_kernel, cudaFuncAttributeMaxDynamicSharedMemorySize, (int)smem);

    prep_kernel<<<M / 64, 256>>>(y);
    gmm_kernel<<<dim3(N / 128, 4), THREADS, smem>>>(x, t, M);
    combine_kernel<<<(N + 7) / 8, 256>>>(x, t, out, N);
}